// round 13
// baseline (speedup 1.0000x reference)
#include <cuda_runtime.h>
#include <cstdint>

// StochasticAttention collapses algebraically:
//   attention[b,q,v] = sum_f x[b,v,f] * (sum_d w_value[d,f])   (independent of q)
// and out[b,q,:] == rowsum[b,:] for every q — each 4KB output row is identical.
//
// Single launch, 128 blocks (1/SM, all co-resident). Block (b,chunk):
//  Phase A: read contiguous 512KB x slice, compute 128 row-dots -> g_rowsum.
//  Per-batch barrier (8 blocks) via monotonic flag + departure-reset (replay-safe).
//  Phase B: write 128 full q-rows = contiguous 512KB streaming stores
//           (memcpy-like DRAM page locality, unlike the old 4KB-strided 128B writes).

#define FDIM 1024
#define BDIM 16
#define DDIM 64

__device__ __align__(16) float g_rowsum[BDIM * FDIM];
__device__ int g_flag[BDIM];    // producers arrived (0..8), reset by last departer
__device__ int g_depart[BDIM];  // consumers departed (0..8)

struct U4 { uint64_t a, b, c, d; };

__device__ __forceinline__ U4 ldg_pin32(const void* p) {
    U4 v;
    asm volatile("ld.global.nc.L2::evict_last.v4.b64 {%0,%1,%2,%3}, [%4];"
                 : "=l"(v.a), "=l"(v.b), "=l"(v.c), "=l"(v.d) : "l"(p));
    return v;
}
__device__ __forceinline__ void stg_stream32(void* p, float4 v0, float4 v1) {
    uint64_t a = ((uint64_t)__float_as_uint(v0.y) << 32) | __float_as_uint(v0.x);
    uint64_t b = ((uint64_t)__float_as_uint(v0.w) << 32) | __float_as_uint(v0.z);
    uint64_t c = ((uint64_t)__float_as_uint(v1.y) << 32) | __float_as_uint(v1.x);
    uint64_t d = ((uint64_t)__float_as_uint(v1.w) << 32) | __float_as_uint(v1.z);
    asm volatile("st.global.L2::evict_first.v4.b64 [%0], {%1,%2,%3,%4};"
                 :: "l"(p), "l"(a), "l"(b), "l"(c), "l"(d) : "memory");
}
__device__ __forceinline__ float flo(uint64_t u) { return __uint_as_float((unsigned)u); }
__device__ __forceinline__ float fhi(uint64_t u) { return __uint_as_float((unsigned)(u >> 32)); }

__global__ __launch_bounds__(1024, 1)
void k_fused(const float* __restrict__ x,
             const float* __restrict__ w_value,
             float* __restrict__ out) {
    __shared__ __align__(16) float4 s_part[4][FDIM / 4];  // 16 KB
    __shared__ __align__(16) float4 s_wsum[FDIM / 4];     // 4 KB
    __shared__ __align__(16) float4 s_vec[FDIM / 4];      // 4 KB (batch rowsum vector)

    const int tid  = threadIdx.x;
    const int warp = tid >> 5;
    const int lane = tid & 31;
    const int b     = blockIdx.x >> 3;
    const int chunk = blockIdx.x & 7;

    const char* xbytes = reinterpret_cast<const char*>(x);
    const unsigned rowbase = ((unsigned)b << 10) + ((unsigned)chunk << 7);

    // ---- Prefetch first row per warp (hides wsum-phase latency) ----
    U4 a[4];
    {
        const char* xr = xbytes + (size_t)(rowbase + warp * 4) * (FDIM * 4);
#pragma unroll
        for (int t = 0; t < 4; ++t) a[t] = ldg_pin32(xr + (t * 32 + lane) * 32);
    }

    // ---- wsum = column-sum of w_value [D, F] (256KB, L2-deduped) ----
    {
        const int c   = tid & 255;
        const int seg = tid >> 8;
        const float4* w4 = reinterpret_cast<const float4*>(w_value);
        float4 acc = make_float4(0.f, 0.f, 0.f, 0.f);
#pragma unroll
        for (int d = 0; d < DDIM / 4; ++d) {
            float4 v = w4[(size_t)(seg * (DDIM / 4) + d) * (FDIM / 4) + c];
            acc.x += v.x; acc.y += v.y; acc.z += v.z; acc.w += v.w;
        }
        s_part[seg][c] = acc;
    }
    __syncthreads();
    if (tid < FDIM / 4) {
        float4 p0 = s_part[0][tid], p1 = s_part[1][tid];
        float4 p2 = s_part[2][tid], p3 = s_part[3][tid];
        float4 r;
        r.x = p0.x + p1.x + p2.x + p3.x;
        r.y = p0.y + p1.y + p2.y + p3.y;
        r.z = p0.z + p1.z + p2.z + p3.z;
        r.w = p0.w + p1.w + p2.w + p3.w;
        s_wsum[tid] = r;
    }
    __syncthreads();

    // ---- Phase A: 128 row-dots (warp w: rows w*4 .. w*4+3) ----
#pragma unroll
    for (int r = 0; r < 4; ++r) {
        float acc = 0.f;
#pragma unroll
        for (int t = 0; t < 4; ++t) {
            const int c = t * 32 + lane;
            float4 w0 = s_wsum[2 * c];
            float4 w1 = s_wsum[2 * c + 1];
            acc += flo(a[t].a) * w0.x + fhi(a[t].a) * w0.y
                 + flo(a[t].b) * w0.z + fhi(a[t].b) * w0.w
                 + flo(a[t].c) * w1.x + fhi(a[t].c) * w1.y
                 + flo(a[t].d) * w1.z + fhi(a[t].d) * w1.w;
        }
        if (r < 3) {
            const char* xr = xbytes + (size_t)(rowbase + warp * 4 + r + 1) * (FDIM * 4);
#pragma unroll
            for (int t = 0; t < 4; ++t) a[t] = ldg_pin32(xr + (t * 32 + lane) * 32);
        }
#pragma unroll
        for (int off = 16; off; off >>= 1)
            acc += __shfl_xor_sync(0xffffffffu, acc, off);
        if (lane == 0) g_rowsum[rowbase + warp * 4 + r] = acc;
    }

    // ---- Per-batch barrier: 8 producer blocks -> 8 consumer blocks ----
    __syncthreads();          // all g_rowsum stores issued
    __threadfence();          // visible device-wide
    if (tid == 0) {
        atomicAdd(&g_flag[b], 1);
        while (atomicAdd(&g_flag[b], 0) < 8) { }
    }
    __syncthreads();
    __threadfence();          // acquire: rowsum reads see producers' writes

    // ---- Load full rowsum[b,:] (4KB) ----
    if (tid < FDIM / 4)
        s_vec[tid] = reinterpret_cast<const float4*>(g_rowsum)[(b << 8) + tid];
    __syncthreads();

    // ---- Phase B: write 128 contiguous q-rows (512KB streaming) ----
    // tid -> (qsub = tid>>7 in 0..7, col2 = tid&127 selects 32B chunk of the 4KB row)
    const int col2 = tid & 127;
    const int qsub = tid >> 7;
    const float4 v0 = s_vec[col2 * 2];
    const float4 v1 = s_vec[col2 * 2 + 1];
    float4* out4 = reinterpret_cast<float4*>(out);
    const unsigned qstart = ((unsigned)chunk << 7);
#pragma unroll
    for (int i = 0; i < 16; ++i) {
        unsigned q = qstart + (unsigned)i * 8u + (unsigned)qsub;
        stg_stream32(out4 + ((unsigned)b << 18) + q * (FDIM / 4) + (unsigned)(col2 * 2),
                     v0, v1);
    }

    // ---- Departure reset (replay-safe): last block of batch zeroes counters ----
    __syncthreads();
    if (tid == 0) {
        int d = atomicAdd(&g_depart[b], 1);
        if (d == 7) {
            atomicExch(&g_flag[b], 0);
            atomicExch(&g_depart[b], 0);
        }
    }
}

extern "C" void kernel_launch(void* const* d_in, const int* in_sizes, int n_in,
                              void* d_out, int out_size) {
    const float* x       = (const float*)d_in[0];  // [B,F,F]
    const float* w_value = (const float*)d_in[4];  // [D,F]
    float* out = (float*)d_out;                    // [B,F,F]
    (void)in_sizes; (void)n_in; (void)out_size;

    k_fused<<<BDIM * (FDIM / 128), 1024>>>(x, w_value, out);
}

// round 14
// speedup vs baseline: 1.2122x; 1.2122x over previous
#include <cuda_runtime.h>
#include <cstdint>

// StochasticAttention collapses algebraically:
//   attention[b,q,v] = sum_f x[b,v,f] * (sum_d w_value[d,f])   (independent of q)
//
// Two kernels overlapped via PDL: k_wsum (32 blocks, ~1us) computes the global
// column-sum of w_value; k_fused launches programmatically-dependent, issues its
// x prefetch first, then grid-dependency-syncs before reading g_wsum. Hints:
// x loads pinned in L2 (evict_last), out stores streamed (evict_first) — the
// R12-proven pair. Interleaved read/write sub-chunks (no phase lockstep).

#define FDIM 1024
#define BDIM 16
#define DDIM 64

__device__ __align__(16) float g_wsum[FDIM];

struct U4 { uint64_t a, b, c, d; };

__device__ __forceinline__ U4 ldg_pin32(const void* p) {
    U4 v;
    asm volatile("ld.global.nc.L2::evict_last.v4.b64 {%0,%1,%2,%3}, [%4];"
                 : "=l"(v.a), "=l"(v.b), "=l"(v.c), "=l"(v.d) : "l"(p));
    return v;
}
__device__ __forceinline__ void stg_stream32(void* p, float4 v0, float4 v1) {
    uint64_t a = ((uint64_t)__float_as_uint(v0.y) << 32) | __float_as_uint(v0.x);
    uint64_t b = ((uint64_t)__float_as_uint(v0.w) << 32) | __float_as_uint(v0.z);
    uint64_t c = ((uint64_t)__float_as_uint(v1.y) << 32) | __float_as_uint(v1.x);
    uint64_t d = ((uint64_t)__float_as_uint(v1.w) << 32) | __float_as_uint(v1.z);
    asm volatile("st.global.L2::evict_first.v4.b64 [%0], {%1,%2,%3,%4};"
                 :: "l"(p), "l"(a), "l"(b), "l"(c), "l"(d) : "memory");
}
__device__ __forceinline__ float flo(uint64_t u) { return __uint_as_float((unsigned)u); }
__device__ __forceinline__ float fhi(uint64_t u) { return __uint_as_float((unsigned)(u >> 32)); }

// ---- wsum = column-sum of w_value [D, F] (32 blocks, parallel) ----
__global__ void k_wsum(const float* __restrict__ w_value) {
    __shared__ __align__(16) float4 part[32][8];
    const int col  = threadIdx.x & 7;
    const int dg   = threadIdx.x >> 3;
    const int gcol = blockIdx.x * 8 + col;
    const float4* w4 = reinterpret_cast<const float4*>(w_value);
    float4 a = w4[(size_t)(2 * dg)     * (FDIM / 4) + gcol];
    float4 b = w4[(size_t)(2 * dg + 1) * (FDIM / 4) + gcol];
    float4 s;
    s.x = a.x + b.x; s.y = a.y + b.y; s.z = a.z + b.z; s.w = a.w + b.w;
    part[dg][col] = s;
    __syncthreads();
    if (threadIdx.x < 8) {
        float4 acc = part[0][threadIdx.x];
#pragma unroll
        for (int k = 1; k < 32; ++k) {
            float4 p = part[k][threadIdx.x];
            acc.x += p.x; acc.y += p.y; acc.z += p.z; acc.w += p.w;
        }
        reinterpret_cast<float4*>(g_wsum)[blockIdx.x * 8 + threadIdx.x] = acc;
    }
    __threadfence();
    cudaTriggerProgrammaticLaunchCompletion();
}

__global__ __launch_bounds__(1024, 1)
void k_fused(const float* __restrict__ x, float* __restrict__ out) {
    __shared__ __align__(16) float4 s_wsum[FDIM / 4];  // 4 KB
    __shared__ __align__(16) float  s_row[4][32];

    const int tid  = threadIdx.x;
    const int warp = tid >> 5;
    const int lane = tid & 31;
    const int b     = blockIdx.x >> 3;
    const int chunk = blockIdx.x & 7;

    const char* xbytes = reinterpret_cast<const char*>(x);
    const unsigned rowbase = ((unsigned)b << 10) + ((unsigned)chunk << 7);

    // ---- Prefetch sub-chunk 0 BEFORE the grid dependency sync (overlaps k_wsum) ----
    U4 a[4];
    {
        const char* xr = xbytes + (size_t)(rowbase + warp) * (FDIM * 4);
#pragma unroll
        for (int t = 0; t < 4; ++t) a[t] = ldg_pin32(xr + (t * 32 + lane) * 32);
    }

    // ---- Wait for k_wsum, then pull 4KB g_wsum into shared ----
    cudaGridDependencySynchronize();
    if (tid < FDIM / 4)
        s_wsum[tid] = reinterpret_cast<const float4*>(g_wsum)[tid];
    __syncthreads();

    // ---- Pipelined sub-chunks: 32 rows each (R12-proven) ----
    float4* out4 = reinterpret_cast<float4*>(out);
    const int qoff = lane >> 2;
    const int col2 = lane & 3;
    const unsigned obase = ((unsigned)b << 18) + ((unsigned)chunk << 5);

#pragma unroll
    for (int s = 0; s < 4; ++s) {
        float acc = 0.f;
#pragma unroll
        for (int t = 0; t < 4; ++t) {
            const int c = t * 32 + lane;
            float4 w0 = s_wsum[2 * c];
            float4 w1 = s_wsum[2 * c + 1];
            acc += flo(a[t].a) * w0.x + fhi(a[t].a) * w0.y
                 + flo(a[t].b) * w0.z + fhi(a[t].b) * w0.w
                 + flo(a[t].c) * w1.x + fhi(a[t].c) * w1.y
                 + flo(a[t].d) * w1.z + fhi(a[t].d) * w1.w;
        }
        if (s < 3) {
            const char* xr = xbytes + (size_t)(rowbase + (s + 1) * 32 + warp) * (FDIM * 4);
#pragma unroll
            for (int t = 0; t < 4; ++t) a[t] = ldg_pin32(xr + (t * 32 + lane) * 32);
        }
#pragma unroll
        for (int off = 16; off; off >>= 1)
            acc += __shfl_xor_sync(0xffffffffu, acc, off);
        if (lane == 0) s_row[s][warp] = acc;
        __syncthreads();

        const float4 v0 = reinterpret_cast<const float4*>(s_row[s])[col2 * 2];
        const float4 v1 = reinterpret_cast<const float4*>(s_row[s])[col2 * 2 + 1];
        const unsigned vbase = obase + ((unsigned)s << 3);
#pragma unroll
        for (int it = 0; it < 4; ++it) {
            unsigned q = (unsigned)it * 256u + (unsigned)warp * 8u + (unsigned)qoff;
            stg_stream32(out4 + vbase + q * (FDIM / 4) + (unsigned)(col2 * 2), v0, v1);
        }
    }
}

extern "C" void kernel_launch(void* const* d_in, const int* in_sizes, int n_in,
                              void* d_out, int out_size) {
    const float* x       = (const float*)d_in[0];  // [B,F,F]
    const float* w_value = (const float*)d_in[4];  // [D,F]
    float* out = (float*)d_out;                    // [B,F,F]
    (void)in_sizes; (void)n_in; (void)out_size;

    k_wsum<<<32, 256>>>(w_value);

    cudaLaunchConfig_t cfg = {};
    cfg.gridDim  = dim3(BDIM * (FDIM / 128));
    cfg.blockDim = dim3(1024);
    cfg.dynamicSmemBytes = 0;
    cfg.stream = 0;
    cudaLaunchAttribute attr[1];
    attr[0].id = cudaLaunchAttributeProgrammaticStreamSerialization;
    attr[0].val.programmaticStreamSerializationAllowed = 1;
    cfg.attrs = attr;
    cfg.numAttrs = 1;
    cudaLaunchKernelEx(&cfg, k_fused, x, out);
}